// round 9
// baseline (speedup 1.0000x reference)
#include <cuda_runtime.h>

// Shapes (fixed by the problem)
#define B_       32
#define QL       4
#define KVLEN    4096
#define HQ       32
#define HKV      8
#define D_       128
#define G_       4
#define ROWS     16                 // G_*QL query rows per (b, h_kv)
#define C        64                 // kv positions per chunk
#define NCHUNK   (KVLEN / C)        // 64
#define NTHREADS 256
#define BOUND    (KVLEN - QL)       // 4092: ki >= BOUND comes from new key/value
#define KPAD     132                // padded K row (floats): stride 4 banks -> conflict-free LDS.128

typedef unsigned long long u64;

// Packed fp32x2 FMA (sm_100+): 2 MACs per issue slot.
__device__ __forceinline__ void fma2(u64 &acc, u64 a, u64 b) {
    asm("fma.rn.f32x2 %0, %1, %2, %0;" : "+l"(acc) : "l"(a), "l"(b));
}
__device__ __forceinline__ float2 u2f(u64 v) {
    float2 r; asm("mov.b64 {%0,%1}, %2;" : "=f"(r.x), "=f"(r.y) : "l"(v)); return r;
}
__device__ __forceinline__ u64 f2u(float x, float y) {
    u64 r; asm("mov.b64 %0, {%1,%2};" : "=l"(r) : "f"(x), "f"(y)); return r;
}
__device__ __forceinline__ unsigned saddr(const void* p) {
    return (unsigned)__cvta_generic_to_shared(p);
}
__device__ __forceinline__ void cpasync16(unsigned dst, const float* src) {
    asm volatile("cp.async.cg.shared.global [%0], [%1], 16;" :: "r"(dst), "l"(src));
}

struct Smem {
    float K[2][C][KPAD];     // 67584 B : double-buffered K chunk
    float Q[ROWS][D_];       //  8192 B
    float P[C][20];          //  5120 B : probs, padded row (conflict-free float4)
    int   rb[2][C];          //   512 B : per-position row base (shared K/V layout)
    float red[ROWS][2];      //   128 B
    float m[ROWS], l[ROWS], alpha[ROWS];
};
#define SMEM_BYTES ((int)sizeof(Smem))

__global__ __launch_bounds__(NTHREADS, 2)
void attn_decode_kernel(const float* __restrict__ query,
                        const float* __restrict__ keyn,
                        const float* __restrict__ valn,
                        const float* __restrict__ kcache,
                        const float* __restrict__ vcache,
                        const int*   __restrict__ btab,
                        float*       __restrict__ out)
{
    extern __shared__ __align__(16) char smem_raw[];
    Smem& sm = *reinterpret_cast<Smem*>(smem_raw);

    const int tid  = threadIdx.x;
    const int lane = tid & 31;
    const int wid  = tid >> 5;
    const int bh   = blockIdx.x;
    const int b    = bh >> 3;     // / HKV
    const int h    = bh & 7;      // % HKV

    const int* btrow = btab + b * (KVLEN / 16);

    // ---- load Q tile: rows r = g*QL + qi ----
    #pragma unroll
    for (int idx = tid; idx < ROWS * D_; idx += NTHREADS) {
        int r = idx >> 7, d = idx & 127;
        int g = r >> 2, qi = r & 3;
        sm.Q[r][d] = query[(size_t)(b * QL + qi) * (HQ * D_) + (h * G_ + g) * D_ + d];
    }
    if (tid < ROWS) { sm.m[tid] = -1e30f; sm.l[tid] = 0.0f; }

    // phase-1 & phase-3 thread mapping
    const int pos = tid & 63;      // kv position within chunk (phase 1)
    const int rg  = tid >> 6;      // row group: rows rg*4 .. rg*4+3
    const int d2  = (tid & 63) * 2; // dim pair (phase 3)

    u64 o64[4] = {0ull, 0ull, 0ull, 0ull};
    const float scale = 0.08838834764831845f;  // 1/sqrt(128)

    // ---- prime pipeline: load chunk 0 ----
    {
        #pragma unroll
        for (int i = 0; i < 8; i++) {
            const int row = wid + i * 8;
            const int ki = row;                    // chunk 0
            int bt = btrow[ki >> 4];
            int rbase = (bt * 16 + (ki & 15)) * (HKV * D_) + h * D_;
            if (lane == 0) sm.rb[0][row] = rbase;
            cpasync16(saddr(&sm.K[0][row][lane * 4]), kcache + rbase + lane * 4);
        }
        asm volatile("cp.async.commit_group;" ::: "memory");
    }

    for (int t = 0; t < NCHUNK; t++) {
        const int buf  = t & 1;
        const int base = t * C;

        // wait for chunk t's K data
        asm volatile("cp.async.wait_group 0;" ::: "memory");
        __syncthreads();   // S0: chunk t visible; phase3(t-1) done -> safe to overwrite buf^1

        // ---- issue prefetch of chunk t+1 into buf^1 ----
        if (t + 1 < NCHUNK) {
            const int nbase = base + C;
            #pragma unroll
            for (int i = 0; i < 8; i++) {
                const int row = wid + i * 8;
                const int ki = nbase + row;
                int rbase; const float* src;
                if (ki >= BOUND) {
                    rbase = (b * QL + (ki - BOUND)) * (HKV * D_) + h * D_;
                    src = keyn;
                } else {
                    int bt = btrow[ki >> 4];
                    rbase = (bt * 16 + (ki & 15)) * (HKV * D_) + h * D_;
                    src = kcache;
                }
                if (lane == 0) sm.rb[buf ^ 1][row] = rbase;
                cpasync16(saddr(&sm.K[buf ^ 1][row][lane * 4]), src + rbase + lane * 4);
            }
        }
        asm volatile("cp.async.commit_group;" ::: "memory");

        // ================= phase 1: scores =================
        // thread (pos, rg): rows rg*4..rg*4+3 against kv position base+pos
        u64 acc[4] = {0ull, 0ull, 0ull, 0ull};
        const float* krow = &sm.K[buf][pos][0];
        #pragma unroll 8
        for (int c = 0; c < 32; c++) {
            ulonglong2 k2 = *reinterpret_cast<const ulonglong2*>(krow + c * 4); // conflict-free LDS.128
            #pragma unroll
            for (int rr = 0; rr < 4; rr++) {
                ulonglong2 q2 = *reinterpret_cast<const ulonglong2*>(&sm.Q[rg * 4 + rr][c * 4]); // broadcast
                fma2(acc[rr], q2.x, k2.x);
                fma2(acc[rr], q2.y, k2.y);
            }
        }

        const int ki = base + pos;
        float s[4];
        #pragma unroll
        for (int rr = 0; rr < 4; rr++) {
            float2 a = u2f(acc[rr]);
            s[rr] = (a.x + a.y) * scale;
            if (ki - rr > BOUND) s[rr] = -1e30f;   // causal mask (qi = rr)
        }

        // ================= phase 2: online softmax =================
        // row r = rg*4+rr owned by warps 2rg, 2rg+1
        #pragma unroll
        for (int rr = 0; rr < 4; rr++) {
            float v = s[rr];
            v = fmaxf(v, __shfl_xor_sync(0xffffffffu, v, 16));
            v = fmaxf(v, __shfl_xor_sync(0xffffffffu, v, 8));
            v = fmaxf(v, __shfl_xor_sync(0xffffffffu, v, 4));
            v = fmaxf(v, __shfl_xor_sync(0xffffffffu, v, 2));
            v = fmaxf(v, __shfl_xor_sync(0xffffffffu, v, 1));
            if (lane == 0) sm.red[rg * 4 + rr][wid & 1] = v;
        }
        __syncthreads();   // S1
        if (tid < ROWS) {
            float tm = fmaxf(sm.red[tid][0], sm.red[tid][1]);
            float mo = sm.m[tid];
            float mn = fmaxf(mo, tm);
            sm.alpha[tid] = __expf(mo - mn);
            sm.m[tid] = mn;
        }
        __syncthreads();   // S2

        // p = exp(s - m_new); stage into P; warp sum reduce
        {
            float4 p;
            p.x = __expf(s[0] - sm.m[rg * 4 + 0]);
            p.y = __expf(s[1] - sm.m[rg * 4 + 1]);
            p.z = __expf(s[2] - sm.m[rg * 4 + 2]);
            p.w = __expf(s[3] - sm.m[rg * 4 + 3]);
            *reinterpret_cast<float4*>(&sm.P[pos][rg * 4]) = p;
            s[0] = p.x; s[1] = p.y; s[2] = p.z; s[3] = p.w;
        }
        #pragma unroll
        for (int rr = 0; rr < 4; rr++) {
            float v = s[rr];
            v += __shfl_xor_sync(0xffffffffu, v, 16);
            v += __shfl_xor_sync(0xffffffffu, v, 8);
            v += __shfl_xor_sync(0xffffffffu, v, 4);
            v += __shfl_xor_sync(0xffffffffu, v, 2);
            v += __shfl_xor_sync(0xffffffffu, v, 1);
            if (lane == 0) sm.red[rg * 4 + rr][wid & 1] = v;
        }
        __syncthreads();   // S3
        if (tid < ROWS) {
            float ts = sm.red[tid][0] + sm.red[tid][1];
            sm.l[tid] = sm.l[tid] * sm.alpha[tid] + ts;
        }

        // ================= phase 3: O += P * V =================
        #pragma unroll
        for (int rr = 0; rr < 4; rr++) {
            float a = sm.alpha[rg * 4 + rr];
            float2 o = u2f(o64[rr]);
            o64[rr] = f2u(o.x * a, o.y * a);
        }

        const int* rbp = sm.rb[buf];
        if (t + 1 < NCHUNK) {
            // fast path: whole chunk from value_cache
            #pragma unroll 8
            for (int jj = 0; jj < C; jj++) {
                int rb = rbp[jj];                                        // LDS broadcast
                u64 v2 = *reinterpret_cast<const u64*>(vcache + rb + d2); // coalesced LDG.64
                float4 p4 = *reinterpret_cast<const float4*>(&sm.P[jj][rg * 4]); // broadcast
                fma2(o64[0], f2u(p4.x, p4.x), v2);
                fma2(o64[1], f2u(p4.y, p4.y), v2);
                fma2(o64[2], f2u(p4.z, p4.z), v2);
                fma2(o64[3], f2u(p4.w, p4.w), v2);
            }
        } else {
            // boundary chunk: last QL positions come from new value tensor
            #pragma unroll 4
            for (int jj = 0; jj < C; jj++) {
                int rb = rbp[jj];
                const float* vsrc = (base + jj >= BOUND) ? valn : vcache;
                u64 v2 = *reinterpret_cast<const u64*>(vsrc + rb + d2);
                float4 p4 = *reinterpret_cast<const float4*>(&sm.P[jj][rg * 4]);
                fma2(o64[0], f2u(p4.x, p4.x), v2);
                fma2(o64[1], f2u(p4.y, p4.y), v2);
                fma2(o64[2], f2u(p4.z, p4.z), v2);
                fma2(o64[3], f2u(p4.w, p4.w), v2);
            }
        }
        // no trailing barrier: next iteration's S0 separates phase3(t) from loader(t+2)
    }

    __syncthreads();   // l_s final values visible

    // ================= epilogue: normalize and store =================
    #pragma unroll
    for (int rr = 0; rr < 4; rr++) {
        int r = rg * 4 + rr;
        float inv = 1.0f / sm.l[r];
        float2 o = u2f(o64[rr]);
        int g = r >> 2, qi = r & 3;
        float2 res = make_float2(o.x * inv, o.y * inv);
        *reinterpret_cast<float2*>(out + (size_t)(b * QL + qi) * (HQ * D_)
                                       + (h * G_ + g) * D_ + d2) = res;
    }
}

extern "C" void kernel_launch(void* const* d_in, const int* in_sizes, int n_in,
                              void* d_out, int out_size) {
    (void)in_sizes; (void)n_in; (void)out_size;
    const float* query        = (const float*)d_in[0];
    const float* key_new      = (const float*)d_in[1];
    const float* value_new    = (const float*)d_in[2];
    const float* key_cache    = (const float*)d_in[3];
    const float* value_cache  = (const float*)d_in[4];
    const int*   block_tables = (const int*)  d_in[5];
    // d_in[6] (new_cache_slots) is implied: last QL positions of each sequence.

    cudaFuncSetAttribute(attn_decode_kernel,
                         cudaFuncAttributeMaxDynamicSharedMemorySize, SMEM_BYTES);
    attn_decode_kernel<<<B_ * HKV, NTHREADS, SMEM_BYTES>>>(
        query, key_new, value_new, key_cache, value_cache,
        block_tables, (float*)d_out);
}

// round 10
// speedup vs baseline: 1.4225x; 1.4225x over previous
#include <cuda_runtime.h>

// Shapes (fixed by the problem)
#define B_       32
#define QL       4
#define KVLEN    4096
#define HQ       32
#define HKV      8
#define D_       128
#define G_       4
#define ROWS     16                 // G_*QL query rows per (b, h_kv)
#define C        64                 // kv positions per chunk
#define NCHUNK   (KVLEN / C)        // 64
#define NTHREADS 256
#define BOUND    (KVLEN - QL)       // 4092: ki >= BOUND comes from new key/value

typedef unsigned long long u64;

__device__ __forceinline__ void fma2(u64 &acc, u64 a, u64 b) {
    asm("fma.rn.f32x2 %0, %1, %2, %0;" : "+l"(acc) : "l"(a), "l"(b));
}
__device__ __forceinline__ float2 u2f(u64 v) {
    float2 r; asm("mov.b64 {%0,%1}, %2;" : "=f"(r.x), "=f"(r.y) : "l"(v)); return r;
}
__device__ __forceinline__ u64 f2u(float x, float y) {
    u64 r; asm("mov.b64 %0, {%1,%2};" : "=l"(r) : "f"(x), "f"(y)); return r;
}
__device__ __forceinline__ unsigned saddr(const void* p) {
    return (unsigned)__cvta_generic_to_shared(p);
}
__device__ __forceinline__ void cpasync16(unsigned dst, const float* src) {
    asm volatile("cp.async.cg.shared.global [%0], [%1], 16;" :: "r"(dst), "l"(src));
}
#define CP_COMMIT() asm volatile("cp.async.commit_group;" ::: "memory")
#define CP_WAIT(n)  asm volatile("cp.async.wait_group %0;" :: "n"(n) : "memory")

struct __align__(16) Smem {
    float slot[3][C][D_];   // 98304 B : rotating K/V chunk slots (K swizzled, V linear)
    float Q[ROWS][D_];      //  8192 B
    float P[C][20];         //  5120 B : probs, padded row
    float redm[ROWS][2];    //   128 B : per-row max partials (2 warps per row)
    float reds[ROWS][2];    //   128 B : per-row sum partials
    int   bt[KVLEN / 16];   //  1024 B : this sequence's block table
};
#define SMEM_BYTES ((int)sizeof(Smem))   // 112896

// Load one 64-position chunk of K or V (8 rows per warp, 16B per lane).
// SWZ: XOR-swizzled layout (for K, conflict-free per-row LDS.128 in phase 1).
template<bool SWZ>
__device__ __forceinline__ void load_chunk(float* dstbase, const int* bt_s, int tc,
                                           int b, int h,
                                           const float* cache, const float* newt,
                                           int wid, int lane)
{
    #pragma unroll
    for (int i = 0; i < 8; i++) {
        const int row = wid * 8 + i;
        const int ki  = tc * C + row;
        const float* src; int rbase;
        if (ki >= BOUND) {
            rbase = (b * QL + (ki - BOUND)) * (HKV * D_) + h * D_;
            src   = newt;
        } else {
            int bt = bt_s[ki >> 4];
            rbase = (bt * 16 + (ki & 15)) * (HKV * D_) + h * D_;
            src   = cache;
        }
        const int woff = SWZ ? ((lane ^ (row & 31)) << 2) : (lane << 2);
        cpasync16(saddr(dstbase + row * D_ + woff), src + rbase + lane * 4);
    }
}

__global__ __launch_bounds__(NTHREADS, 2)
void attn_decode_kernel(const float* __restrict__ query,
                        const float* __restrict__ keyn,
                        const float* __restrict__ valn,
                        const float* __restrict__ kcache,
                        const float* __restrict__ vcache,
                        const int*   __restrict__ btab,
                        float*       __restrict__ out)
{
    extern __shared__ __align__(16) char smem_raw[];
    Smem& sm = *reinterpret_cast<Smem*>(smem_raw);

    const int tid  = threadIdx.x;
    const int lane = tid & 31;
    const int wid  = tid >> 5;
    const int bh   = blockIdx.x;
    const int b    = bh >> 3;
    const int h    = bh & 7;

    // ---- cache block table row, load Q tile ----
    if (tid < KVLEN / 16) sm.bt[tid] = btab[b * (KVLEN / 16) + tid];
    #pragma unroll
    for (int idx = tid; idx < ROWS * D_; idx += NTHREADS) {
        int r = idx >> 7, d = idx & 127;
        int g = r >> 2, qi = r & 3;
        sm.Q[r][d] = query[(size_t)(b * QL + qi) * (HQ * D_) + (h * G_ + g) * D_ + d];
    }

    const int pos = tid & 63;       // kv position within chunk (phase 1)
    const int pm  = pos & 31;       // swizzle key
    const int rg  = tid >> 6;       // row group: rows rg*4 .. rg*4+3
    const int d2  = (tid & 63) * 2; // dim pair (phase 3)

    u64   o64[4] = {0ull, 0ull, 0ull, 0ull};
    float m_r[4] = {-1e30f, -1e30f, -1e30f, -1e30f};
    float l_r[4] = {0.f, 0.f, 0.f, 0.f};
    const float scale = 0.08838834764831845f;  // 1/sqrt(128)

    // ---- prologue: K(0) -> slot0, V(0) -> slot2 ----
    // (bt not in smem yet for chunk 0: compute from global btab directly is avoided by
    //  syncing first — cheap, happens once)
    __syncthreads();
    load_chunk<true >(&sm.slot[0][0][0], sm.bt, 0, b, h, kcache, keyn, wid, lane); CP_COMMIT();
    load_chunk<false>(&sm.slot[2][0][0], sm.bt, 0, b, h, vcache, valn, wid, lane); CP_COMMIT();

    int sk = 0;   // K(t) slot = t % 3
    for (int t = 0; t < NCHUNK; t++) {
        const int skn = (sk + 1 < 3) ? sk + 1 : 0;      // (t+1)%3 : next K slot
        const int sv  = (sk + 2 < 3) ? sk + 2 : sk - 1; // (t+2)%3 == (t-1)%3 : V(t) slot

        // A/B: K(t) ready; CTA-wide visibility; phase3(t-1) finished with slot skn
        CP_WAIT(1);
        __syncthreads();                                 // S0

        // C: prefetch K(t+1) into slot skn
        if (t + 1 < NCHUNK)
            load_chunk<true>(&sm.slot[skn][0][0], sm.bt, t + 1, b, h, kcache, keyn, wid, lane);
        CP_COMMIT();

        // ================= phase 1: scores =================
        u64 acc[4] = {0ull, 0ull, 0ull, 0ull};
        const float* krow = &sm.slot[sk][pos][0];
        #pragma unroll 8
        for (int c = 0; c < 32; c++) {
            ulonglong2 k2 = *reinterpret_cast<const ulonglong2*>(krow + ((c ^ pm) << 2));
            #pragma unroll
            for (int rr = 0; rr < 4; rr++) {
                ulonglong2 q2 = *reinterpret_cast<const ulonglong2*>(&sm.Q[rg * 4 + rr][c * 4]);
                fma2(acc[rr], q2.x, k2.x);
                fma2(acc[rr], q2.y, k2.y);
            }
        }

        const int ki = t * C + pos;
        float s[4];
        #pragma unroll
        for (int rr = 0; rr < 4; rr++) {
            float2 a = u2f(acc[rr]);
            s[rr] = (a.x + a.y) * scale;
            if (ki - rr > BOUND) s[rr] = -1e30f;   // causal mask (qi = rr)
        }

        // ================= phase 2: online softmax (no serial section) =================
        #pragma unroll
        for (int rr = 0; rr < 4; rr++) {
            float v = s[rr];
            v = fmaxf(v, __shfl_xor_sync(0xffffffffu, v, 16));
            v = fmaxf(v, __shfl_xor_sync(0xffffffffu, v, 8));
            v = fmaxf(v, __shfl_xor_sync(0xffffffffu, v, 4));
            v = fmaxf(v, __shfl_xor_sync(0xffffffffu, v, 2));
            v = fmaxf(v, __shfl_xor_sync(0xffffffffu, v, 1));
            if (lane == 0) sm.redm[rg * 4 + rr][wid & 1] = v;
        }
        __syncthreads();                                 // S1 (also: phase1 done -> slot sk free)

        // F: prefetch V(t+1) into slot sk (just freed by phase 1)
        if (t + 1 < NCHUNK)
            load_chunk<false>(&sm.slot[sk][0][0], sm.bt, t + 1, b, h, vcache, valn, wid, lane);
        CP_COMMIT();

        float alpha[4], pv[4];
        #pragma unroll
        for (int rr = 0; rr < 4; rr++) {
            int r = rg * 4 + rr;
            float tm = fmaxf(sm.redm[r][0], sm.redm[r][1]);
            float mn = fmaxf(m_r[rr], tm);
            alpha[rr] = __expf(m_r[rr] - mn);            // 0 on first chunk
            m_r[rr]   = mn;
            pv[rr]    = __expf(s[rr] - mn);
        }
        *reinterpret_cast<float4*>(&sm.P[pos][rg * 4]) =
            make_float4(pv[0], pv[1], pv[2], pv[3]);
        #pragma unroll
        for (int rr = 0; rr < 4; rr++) {
            float v = pv[rr];
            v += __shfl_xor_sync(0xffffffffu, v, 16);
            v += __shfl_xor_sync(0xffffffffu, v, 8);
            v += __shfl_xor_sync(0xffffffffu, v, 4);
            v += __shfl_xor_sync(0xffffffffu, v, 2);
            v += __shfl_xor_sync(0xffffffffu, v, 1);
            if (lane == 0) sm.reds[rg * 4 + rr][wid & 1] = v;
        }

        // H: V(t) complete (newest 2 pending = K(t+1), V(t+1)); S3 makes all copies,
        //    P, and reds CTA-visible
        CP_WAIT(2);
        __syncthreads();                                 // S3

        #pragma unroll
        for (int rr = 0; rr < 4; rr++) {
            int r = rg * 4 + rr;
            float ts = sm.reds[r][0] + sm.reds[r][1];
            l_r[rr] = l_r[rr] * alpha[rr] + ts;
            float2 o = u2f(o64[rr]);
            o64[rr] = f2u(o.x * alpha[rr], o.y * alpha[rr]);
        }

        // ================= phase 3: O += P * V (V from shared) =================
        const float* vs = &sm.slot[sv][0][0];
        #pragma unroll 16
        for (int jj = 0; jj < C; jj++) {
            u64 v2 = *reinterpret_cast<const u64*>(vs + jj * D_ + d2);           // LDS.64
            float4 p4 = *reinterpret_cast<const float4*>(&sm.P[jj][rg * 4]);     // broadcast
            fma2(o64[0], f2u(p4.x, p4.x), v2);
            fma2(o64[1], f2u(p4.y, p4.y), v2);
            fma2(o64[2], f2u(p4.z, p4.z), v2);
            fma2(o64[3], f2u(p4.w, p4.w), v2);
        }

        sk = skn;
    }

    // ================= epilogue: normalize and store =================
    #pragma unroll
    for (int rr = 0; rr < 4; rr++) {
        int r = rg * 4 + rr;
        float inv = 1.0f / l_r[rr];
        float2 o = u2f(o64[rr]);
        int g = r >> 2, qi = r & 3;
        *reinterpret_cast<float2*>(out + (size_t)(b * QL + qi) * (HQ * D_)
                                       + (h * G_ + g) * D_ + d2)
            = make_float2(o.x * inv, o.y * inv);
    }
}

extern "C" void kernel_launch(void* const* d_in, const int* in_sizes, int n_in,
                              void* d_out, int out_size) {
    (void)in_sizes; (void)n_in; (void)out_size;
    const float* query        = (const float*)d_in[0];
    const float* key_new      = (const float*)d_in[1];
    const float* value_new    = (const float*)d_in[2];
    const float* key_cache    = (const float*)d_in[3];
    const float* value_cache  = (const float*)d_in[4];
    const int*   block_tables = (const int*)  d_in[5];
    // d_in[6] (new_cache_slots) is implied: last QL positions of each sequence.

    cudaFuncSetAttribute(attn_decode_kernel,
                         cudaFuncAttributeMaxDynamicSharedMemorySize, SMEM_BYTES);
    attn_decode_kernel<<<B_ * HKV, NTHREADS, SMEM_BYTES>>>(
        query, key_new, value_new, key_cache, value_cache,
        block_tables, (float*)d_out);
}

// round 11
// speedup vs baseline: 1.4252x; 1.0019x over previous
#include <cuda_runtime.h>

// Shapes (fixed by the problem)
#define B_       32
#define QL       4
#define KVLEN    4096
#define HQ       32
#define HKV      8
#define D_       128
#define G_       4
#define ROWS     16                 // G_*QL query rows per (b, h_kv)
#define C        64                 // kv positions per chunk
#define NCHUNK   (KVLEN / C)        // 64
#define NTHREADS 256
#define BOUND    (KVLEN - QL)       // 4092: ki >= BOUND comes from new key/value

typedef unsigned long long u64;

__device__ __forceinline__ void fma2(u64 &acc, u64 a, u64 b) {
    asm("fma.rn.f32x2 %0, %1, %2, %0;" : "+l"(acc) : "l"(a), "l"(b));
}
__device__ __forceinline__ float2 u2f(u64 v) {
    float2 r; asm("mov.b64 {%0,%1}, %2;" : "=f"(r.x), "=f"(r.y) : "l"(v)); return r;
}
__device__ __forceinline__ u64 f2u(float x, float y) {
    u64 r; asm("mov.b64 %0, {%1,%2};" : "=l"(r) : "f"(x), "f"(y)); return r;
}
__device__ __forceinline__ unsigned saddr(const void* p) {
    return (unsigned)__cvta_generic_to_shared(p);
}
__device__ __forceinline__ void cpasync16(unsigned dst, const float* src) {
    asm volatile("cp.async.cg.shared.global [%0], [%1], 16;" :: "r"(dst), "l"(src));
}
#define CP_COMMIT() asm volatile("cp.async.commit_group;" ::: "memory")
#define CP_WAIT(n)  asm volatile("cp.async.wait_group %0;" :: "n"(n) : "memory")

struct __align__(16) Smem {
    float slot[3][C][D_];   // 98304 B : rotating K/V chunk slots (K swizzled, V linear)
    float Q[ROWS][D_];      //  8192 B
    float P[C][20];         //  5120 B : probs, padded row
    float redm[ROWS][2];    //   128 B : per-row max partials (2 warps per row)
    float reds[ROWS][2];    //   128 B : per-row sum partials
    int   bt[KVLEN / 16];   //  1024 B : this sequence's block table
};
#define SMEM_BYTES ((int)sizeof(Smem))   // 112896

// Load one 64-position chunk of K or V (8 rows per warp, 16B per lane).
// SWZ: XOR-swizzled layout (for K, conflict-free per-row LDS.128 in phase 1).
template<bool SWZ>
__device__ __forceinline__ void load_chunk(float* dstbase, const int* bt_s, int tc,
                                           int b, int h,
                                           const float* cache, const float* newt,
                                           int wid, int lane)
{
    #pragma unroll
    for (int i = 0; i < 8; i++) {
        const int row = wid * 8 + i;
        const int ki  = tc * C + row;
        const float* src; int rbase;
        if (ki >= BOUND) {
            rbase = (b * QL + (ki - BOUND)) * (HKV * D_) + h * D_;
            src   = newt;
        } else {
            int bt = bt_s[ki >> 4];
            rbase = (bt * 16 + (ki & 15)) * (HKV * D_) + h * D_;
            src   = cache;
        }
        const int woff = SWZ ? ((lane ^ (row & 31)) << 2) : (lane << 2);
        cpasync16(saddr(dstbase + row * D_ + woff), src + rbase + lane * 4);
    }
}

__global__ __launch_bounds__(NTHREADS, 2)
void attn_decode_kernel(const float* __restrict__ query,
                        const float* __restrict__ keyn,
                        const float* __restrict__ valn,
                        const float* __restrict__ kcache,
                        const float* __restrict__ vcache,
                        const int*   __restrict__ btab,
                        float*       __restrict__ out)
{
    extern __shared__ __align__(16) char smem_raw[];
    Smem& sm = *reinterpret_cast<Smem*>(smem_raw);

    const int tid  = threadIdx.x;
    const int lane = tid & 31;
    const int wid  = tid >> 5;
    const int bh   = blockIdx.x;
    const int b    = bh >> 3;
    const int h    = bh & 7;

    // ---- cache block table row, load Q tile ----
    if (tid < KVLEN / 16) sm.bt[tid] = btab[b * (KVLEN / 16) + tid];
    #pragma unroll
    for (int idx = tid; idx < ROWS * D_; idx += NTHREADS) {
        int r = idx >> 7, d = idx & 127;
        int g = r >> 2, qi = r & 3;
        sm.Q[r][d] = query[(size_t)(b * QL + qi) * (HQ * D_) + (h * G_ + g) * D_ + d];
    }

    const int pos = tid & 63;       // kv position within chunk (phase 1)
    const int pm  = pos & 31;       // swizzle key
    const int rg  = tid >> 6;       // row group: rows rg*4 .. rg*4+3
    const int d2  = (tid & 63) * 2; // dim pair (phase 3)

    u64   o64[4] = {0ull, 0ull, 0ull, 0ull};
    float m_r[4] = {-1e30f, -1e30f, -1e30f, -1e30f};
    float l_r[4] = {0.f, 0.f, 0.f, 0.f};
    const float scale = 0.08838834764831845f;  // 1/sqrt(128)

    // ---- prologue: K(0) -> slot0, V(0) -> slot2 ----
    // (bt not in smem yet for chunk 0: compute from global btab directly is avoided by
    //  syncing first — cheap, happens once)
    __syncthreads();
    load_chunk<true >(&sm.slot[0][0][0], sm.bt, 0, b, h, kcache, keyn, wid, lane); CP_COMMIT();
    load_chunk<false>(&sm.slot[2][0][0], sm.bt, 0, b, h, vcache, valn, wid, lane); CP_COMMIT();

    int sk = 0;   // K(t) slot = t % 3
    for (int t = 0; t < NCHUNK; t++) {
        const int skn = (sk + 1 < 3) ? sk + 1 : 0;      // (t+1)%3 : next K slot
        const int sv  = (sk + 2 < 3) ? sk + 2 : sk - 1; // (t+2)%3 == (t-1)%3 : V(t) slot

        // A/B: K(t) ready; CTA-wide visibility; phase3(t-1) finished with slot skn
        CP_WAIT(1);
        __syncthreads();                                 // S0

        // C: prefetch K(t+1) into slot skn
        if (t + 1 < NCHUNK)
            load_chunk<true>(&sm.slot[skn][0][0], sm.bt, t + 1, b, h, kcache, keyn, wid, lane);
        CP_COMMIT();

        // ================= phase 1: scores =================
        u64 acc[4] = {0ull, 0ull, 0ull, 0ull};
        const float* krow = &sm.slot[sk][pos][0];
        #pragma unroll 8
        for (int c = 0; c < 32; c++) {
            ulonglong2 k2 = *reinterpret_cast<const ulonglong2*>(krow + ((c ^ pm) << 2));
            #pragma unroll
            for (int rr = 0; rr < 4; rr++) {
                ulonglong2 q2 = *reinterpret_cast<const ulonglong2*>(&sm.Q[rg * 4 + rr][c * 4]);
                fma2(acc[rr], q2.x, k2.x);
                fma2(acc[rr], q2.y, k2.y);
            }
        }

        const int ki = t * C + pos;
        float s[4];
        #pragma unroll
        for (int rr = 0; rr < 4; rr++) {
            float2 a = u2f(acc[rr]);
            s[rr] = (a.x + a.y) * scale;
            if (ki - rr > BOUND) s[rr] = -1e30f;   // causal mask (qi = rr)
        }

        // ================= phase 2: online softmax (no serial section) =================
        #pragma unroll
        for (int rr = 0; rr < 4; rr++) {
            float v = s[rr];
            v = fmaxf(v, __shfl_xor_sync(0xffffffffu, v, 16));
            v = fmaxf(v, __shfl_xor_sync(0xffffffffu, v, 8));
            v = fmaxf(v, __shfl_xor_sync(0xffffffffu, v, 4));
            v = fmaxf(v, __shfl_xor_sync(0xffffffffu, v, 2));
            v = fmaxf(v, __shfl_xor_sync(0xffffffffu, v, 1));
            if (lane == 0) sm.redm[rg * 4 + rr][wid & 1] = v;
        }
        __syncthreads();                                 // S1 (also: phase1 done -> slot sk free)

        // F: prefetch V(t+1) into slot sk (just freed by phase 1)
        if (t + 1 < NCHUNK)
            load_chunk<false>(&sm.slot[sk][0][0], sm.bt, t + 1, b, h, vcache, valn, wid, lane);
        CP_COMMIT();

        float alpha[4], pv[4];
        #pragma unroll
        for (int rr = 0; rr < 4; rr++) {
            int r = rg * 4 + rr;
            float tm = fmaxf(sm.redm[r][0], sm.redm[r][1]);
            float mn = fmaxf(m_r[rr], tm);
            alpha[rr] = __expf(m_r[rr] - mn);            // 0 on first chunk
            m_r[rr]   = mn;
            pv[rr]    = __expf(s[rr] - mn);
        }
        *reinterpret_cast<float4*>(&sm.P[pos][rg * 4]) =
            make_float4(pv[0], pv[1], pv[2], pv[3]);
        #pragma unroll
        for (int rr = 0; rr < 4; rr++) {
            float v = pv[rr];
            v += __shfl_xor_sync(0xffffffffu, v, 16);
            v += __shfl_xor_sync(0xffffffffu, v, 8);
            v += __shfl_xor_sync(0xffffffffu, v, 4);
            v += __shfl_xor_sync(0xffffffffu, v, 2);
            v += __shfl_xor_sync(0xffffffffu, v, 1);
            if (lane == 0) sm.reds[rg * 4 + rr][wid & 1] = v;
        }

        // H: V(t) complete (newest 2 pending = K(t+1), V(t+1)); S3 makes all copies,
        //    P, and reds CTA-visible
        CP_WAIT(2);
        __syncthreads();                                 // S3

        #pragma unroll
        for (int rr = 0; rr < 4; rr++) {
            int r = rg * 4 + rr;
            float ts = sm.reds[r][0] + sm.reds[r][1];
            l_r[rr] = l_r[rr] * alpha[rr] + ts;
            float2 o = u2f(o64[rr]);
            o64[rr] = f2u(o.x * alpha[rr], o.y * alpha[rr]);
        }

        // ================= phase 3: O += P * V (V from shared) =================
        const float* vs = &sm.slot[sv][0][0];
        #pragma unroll 16
        for (int jj = 0; jj < C; jj++) {
            u64 v2 = *reinterpret_cast<const u64*>(vs + jj * D_ + d2);           // LDS.64
            float4 p4 = *reinterpret_cast<const float4*>(&sm.P[jj][rg * 4]);     // broadcast
            fma2(o64[0], f2u(p4.x, p4.x), v2);
            fma2(o64[1], f2u(p4.y, p4.y), v2);
            fma2(o64[2], f2u(p4.z, p4.z), v2);
            fma2(o64[3], f2u(p4.w, p4.w), v2);
        }

        sk = skn;
    }

    // ================= epilogue: normalize and store =================
    #pragma unroll
    for (int rr = 0; rr < 4; rr++) {
        int r = rg * 4 + rr;
        float inv = 1.0f / l_r[rr];
        float2 o = u2f(o64[rr]);
        int g = r >> 2, qi = r & 3;
        *reinterpret_cast<float2*>(out + (size_t)(b * QL + qi) * (HQ * D_)
                                       + (h * G_ + g) * D_ + d2)
            = make_float2(o.x * inv, o.y * inv);
    }
}

extern "C" void kernel_launch(void* const* d_in, const int* in_sizes, int n_in,
                              void* d_out, int out_size) {
    (void)in_sizes; (void)n_in; (void)out_size;
    const float* query        = (const float*)d_in[0];
    const float* key_new      = (const float*)d_in[1];
    const float* value_new    = (const float*)d_in[2];
    const float* key_cache    = (const float*)d_in[3];
    const float* value_cache  = (const float*)d_in[4];
    const int*   block_tables = (const int*)  d_in[5];
    // d_in[6] (new_cache_slots) is implied: last QL positions of each sequence.

    cudaFuncSetAttribute(attn_decode_kernel,
                         cudaFuncAttributeMaxDynamicSharedMemorySize, SMEM_BYTES);
    attn_decode_kernel<<<B_ * HKV, NTHREADS, SMEM_BYTES>>>(
        query, key_new, value_new, key_cache, value_cache,
        block_tables, (float*)d_out);
}